// round 11
// baseline (speedup 1.0000x reference)
#include <cuda_runtime.h>
#include <math.h>
#include <stdint.h>

#define H 1024
#define VOCAB 50257
#define NB 148                  // persistent: one block per SM
#define NT 512                  // 16 warps
#define TR 16                   // rows per tile
#define TILE_FLOATS (TR * H)
#define TILE_BYTES (TILE_FLOATS * 4)       // 64KB
#define DYN_SMEM (3 * TILE_BYTES)          // 192KB ring
#define LOG_CHUNK 340           // ceil(VOCAB / NB)

// Scratch (__device__ globals — allocation-free rule)
__device__ float g_partA[8192];   // layer1: [0,4096)=Wih·x, [4096,8192)=Whh·h
__device__ float g_partB[8192];   // layer2
__device__ float2 g_pairs[NB];
__device__ unsigned g_cnt[4];
__device__ volatile unsigned g_gen[4];

// ---------------------------------------------------------------------------
__device__ __forceinline__ float sigmoidf_fast(float x) {
    return 1.f / (1.f + __expf(-x));
}

__device__ __forceinline__ void merge_pair(float& m, float& s, float m2, float s2) {
    if (m2 > m) { float t = s; s = s2 + t * __expf(m - m2); m = m2; }
    else if (m2 != -INFINITY) { s += s2 * __expf(m2 - m); }
}

// Grid-wide spin barrier (all NB blocks co-resident; gen monotonic across replays)
__device__ __forceinline__ void gsync(int b) {
    __syncthreads();
    if (threadIdx.x == 0) {
        __threadfence();
        unsigned cur = g_gen[b];
        unsigned pos = atomicAdd(&g_cnt[b], 1u);
        if (pos == NB - 1) {
            g_cnt[b] = 0;
            __threadfence();
            g_gen[b] = cur + 1;
        } else {
            while (g_gen[b] == cur) __nanosleep(32);
        }
        __threadfence();
    }
    __syncthreads();
}

// ---------------------------------------------------------------------------
// mbarrier + cp.async.bulk primitives
// ---------------------------------------------------------------------------
__device__ __forceinline__ uint32_t smem_u32(const void* p) {
    return (uint32_t)__cvta_generic_to_shared(p);
}
__device__ __forceinline__ void mbar_init(uint32_t m) {
    asm volatile("mbarrier.init.shared.b64 [%0], 1;" :: "r"(m) : "memory");
}
__device__ __forceinline__ void mbar_wait(uint32_t m, uint32_t phase) {
    asm volatile(
        "{\n\t.reg .pred P;\n\t"
        "W_%=:\n\t"
        "mbarrier.try_wait.parity.acquire.cta.shared::cta.b64 P, [%0], %1, 0x989680;\n\t"
        "@P bra D_%=;\n\t"
        "bra W_%=;\n\t"
        "D_%=:\n\t}"
        :: "r"(m), "r"(phase) : "memory");
}
// issue one bulk tile copy: expect_tx then cp.async.bulk (thread-0 only)
__device__ __forceinline__ void tile_issue(uint32_t dst, const float* src,
                                           uint32_t bytes, uint32_t mbar) {
    asm volatile("mbarrier.arrive.expect_tx.shared.b64 _, [%0], %1;"
                 :: "r"(mbar), "r"(bytes) : "memory");
    asm volatile("cp.async.bulk.shared::cluster.global.mbarrier::complete_tx::bytes "
                 "[%0], [%1], %2, [%3];"
                 :: "r"(dst), "l"(src), "r"(bytes), "r"(mbar) : "memory");
}
__device__ __forceinline__ void fence_async() {
    asm volatile("fence.proxy.async.shared::cta;" ::: "memory");
}

__device__ __forceinline__ float warp_sum(float acc) {
#pragma unroll
    for (int o = 16; o > 0; o >>= 1) acc += __shfl_down_sync(0xffffffffu, acc, o);
    return acc;
}

// dot of one smem weight row (H floats) against smem vector; warp-collective
__device__ __forceinline__ float smem_row_dot(const float* wrow, const float4* xv, int lane) {
    const float4* w4 = (const float4*)wrow;
    float acc = 0.f;
#pragma unroll
    for (int k = 0; k < 8; k++) {
        float4 w = w4[k * 32 + lane];
        float4 x = xv[k * 32 + lane];
        acc += w.x * x.x + w.y * x.y + w.z * x.z + w.w * x.w;
    }
    return acc;
}

// LSTM elementwise for element j (torch gate order i, f, g, o)
__device__ __forceinline__ void act_phase(
        const float* __restrict__ part,
        const float* __restrict__ bih, const float* __restrict__ bhh,
        float cin, float& hout, float& cout, int j) {
    float gi = part[j]         + part[4096 + j]         + bih[j]         + bhh[j];
    float gf = part[j + H]     + part[4096 + j + H]     + bih[j + H]     + bhh[j + H];
    float gg = part[j + 2 * H] + part[4096 + j + 2 * H] + bih[j + 2 * H] + bhh[j + 2 * H];
    float go = part[j + 3 * H] + part[4096 + j + 3 * H] + bih[j + 3 * H] + bhh[j + 3 * H];
    cout = sigmoidf_fast(gf) * cin + sigmoidf_fast(gi) * tanhf(gg);
    hout = sigmoidf_fast(go) * tanhf(cout);
}

// ---------------------------------------------------------------------------
// Gates streaming: this block handles nrows contiguous rows of W starting at
// r0, dotted against vec, results into part[pbase + r0 + k].
// 3-stage cp.async.bulk pipeline through dynbuf.
// ---------------------------------------------------------------------------
__device__ void stream_gates(const float* __restrict__ W, const float4* vec,
                             float* __restrict__ part, int pbase,
                             int r0, int nrows,
                             float* dynbuf, uint32_t mbase,
                             int t, int lane, int warp) {
    if (nrows <= 0) return;
    int ntiles = (nrows + TR - 1) / TR;
    uint32_t bufu = smem_u32(dynbuf);
    if (t == 0) {
        int pre = ntiles < 3 ? ntiles : 3;
        for (int s = 0; s < pre; s++) {
            int rows = min(TR, nrows - s * TR);
            tile_issue(bufu + s * TILE_BYTES, W + (long)(r0 + s * TR) * H,
                       rows * H * 4, mbase + 8 * s);
        }
    }
    for (int i = 0; i < ntiles; i++) {
        int slot = i % 3;
        mbar_wait(mbase + 8 * slot, (i / 3) & 1);
        int trows = min(TR, nrows - i * TR);
        if (warp < trows) {
            float acc = smem_row_dot(dynbuf + slot * TILE_FLOATS + warp * H, vec, lane);
            acc = warp_sum(acc);
            if (lane == 0) part[pbase + r0 + i * TR + warp] = acc;
        }
        __syncthreads();
        if (t == 0 && i + 3 < ntiles) {
            fence_async();
            int rows = min(TR, nrows - (i + 3) * TR);
            tile_issue(bufu + slot * TILE_BYTES, W + (long)(r0 + (i + 3) * TR) * H,
                       rows * H * 4, mbase + 8 * slot);
        }
    }
}

// ---------------------------------------------------------------------------
// ONE persistent kernel: embed -> gates1 -> act1 -> gates2 -> act2 ->
// logits(+online softmax) -> lse -> subtract. All GEMVs bulk-copy streamed.
// ---------------------------------------------------------------------------
__global__ void __launch_bounds__(NT, 1) decoder_kernel(
        const int* __restrict__ id, const float* __restrict__ h0,
        const float* __restrict__ c0, const float* __restrict__ emb,
        const float* __restrict__ Wih, const float* __restrict__ Whh,
        const float* __restrict__ bih, const float* __restrict__ bhh,
        const float* __restrict__ Wout, const float* __restrict__ bout,
        float* __restrict__ out, int write_tail) {
    extern __shared__ float dynbuf[];          // 3 x 64KB tile ring
    __shared__ float sx[H];
    __shared__ float sh[H];
    __shared__ float2 spair[16];
    __shared__ float s_lse;
    __shared__ int s_nzx, s_nzh;
    __shared__ uint64_t s_mb[9];               // 3 barriers per streaming phase

    int t = threadIdx.x, lane = t & 31, warp = t >> 5, b = blockIdx.x;
    const float4* sx4 = (const float4*)sx;
    const float4* sh4 = (const float4*)sh;
    uint32_t mbase = smem_u32(s_mb);

    // P0: init mbarriers; stage relu(emb[id]) and h0; detect zero vectors
    if (t == 0) {
        for (int s = 0; s < 9; s++) mbar_init(mbase + 8 * s);
        s_nzx = 0; s_nzh = 0;
    }
    __syncthreads();
    {
        const float* e = emb + (long)id[0] * H;
        float x0 = fmaxf(e[t], 0.f),  x1 = fmaxf(e[t + NT], 0.f);
        float hv0 = h0[t],            hv1 = h0[t + NT];
        sx[t] = x0; sx[t + NT] = x1;
        sh[t] = hv0; sh[t + NT] = hv1;
        if (x0 != 0.f || x1 != 0.f) s_nzx = 1;
        if (hv0 != 0.f || hv1 != 0.f) s_nzh = 1;
    }
    __syncthreads();

    // ---- P1: layer-1 gates ----
    {
        bool xz = !s_nzx, hz = !s_nzh;
        // zero-fill inactive partials
        int gi = b * NT + t;
        if (gi < 8192) {
            bool inact = (gi < 4096) ? xz : hz;
            if (inact) g_partA[gi] = 0.f;
        }
        int nact = (!xz) + (!hz);
        if (nact > 0) {
            int bpg = NB / nact;
            int g = min(b / bpg, nact - 1);
            int lb = b - g * bpg;
            bool is_ih = (nact == 2) ? (g == 0) : (!xz);
            const float* W = is_ih ? Wih : Whh;
            const float4* vec = is_ih ? sx4 : sh4;
            int pbase = is_ih ? 0 : 4096;
            int chunk = (4096 + bpg - 1) / bpg;
            int r0 = lb * chunk;
            int nrows = min(4096, r0 + chunk) - r0;
            stream_gates(W, vec, g_partA, pbase, r0, nrows,
                         dynbuf, mbase + 0, t, lane, warp);
        }
    }
    gsync(0);

    // P2: act1 — redundant per block; c1 stays in registers
    float h1a, c1a, h1b, c1b;
    act_phase(g_partA, bih, bhh, c0[t],      h1a, c1a, t);
    act_phase(g_partA, bih, bhh, c0[t + NT], h1b, c1b, t + NT);
    __syncthreads();
    if (t == 0) { s_nzx = 0; s_nzh = 0; }
    __syncthreads();
    {
        float x0 = fmaxf(h1a, 0.f), x1 = fmaxf(h1b, 0.f);
        sx[t] = x0; sx[t + NT] = x1;
        sh[t] = h1a; sh[t + NT] = h1b;
        if (x0 != 0.f || x1 != 0.f) s_nzx = 1;
        if (h1a != 0.f || h1b != 0.f) s_nzh = 1;
    }
    __syncthreads();

    // ---- P3: layer-2 gates (same weights per reference) ----
    {
        bool xz = !s_nzx, hz = !s_nzh;
        int gi = b * NT + t;
        if (gi < 8192) {
            bool inact = (gi < 4096) ? xz : hz;
            if (inact) g_partB[gi] = 0.f;
        }
        int nact = (!xz) + (!hz);
        if (nact > 0) {
            int bpg = NB / nact;
            int g = min(b / bpg, nact - 1);
            int lb = b - g * bpg;
            bool is_ih = (nact == 2) ? (g == 0) : (!xz);
            const float* W = is_ih ? Wih : Whh;
            const float4* vec = is_ih ? sx4 : sh4;
            int pbase = is_ih ? 0 : 4096;
            int chunk = (4096 + bpg - 1) / bpg;
            int r0 = lb * chunk;
            int nrows = min(4096, r0 + chunk) - r0;
            stream_gates(W, vec, g_partB, pbase, r0, nrows,
                         dynbuf, mbase + 24, t, lane, warp);
        }
    }
    gsync(1);

    // P4: act2 — redundant per block; block 0 writes the (h, c) tail
    float h2a, c2a, h2b, c2b;
    act_phase(g_partB, bih, bhh, c1a, h2a, c2a, t);
    act_phase(g_partB, bih, bhh, c1b, h2b, c2b, t + NT);
    __syncthreads();
    sx[t] = h2a; sx[t + NT] = h2b;
    if (write_tail && b == 0) {
        out[VOCAB + t]          = h2a;
        out[VOCAB + t + NT]     = h2b;
        out[VOCAB + H + t]      = c2a;
        out[VOCAB + H + t + NT] = c2b;
    }
    __syncthreads();

    // ---- P5: logits — contiguous per-block chunk, 3-stage bulk pipeline ----
    float m = -INFINITY, s = 0.f;
    {
        int r0 = b * LOG_CHUNK;
        int r1 = min(VOCAB, r0 + LOG_CHUNK);
        int nrows = r1 - r0;
        int ntiles = (nrows + TR - 1) / TR;
        uint32_t bufu = smem_u32(dynbuf);
        uint32_t mb2 = mbase + 48;
        if (t == 0 && nrows > 0) {
            int pre = ntiles < 3 ? ntiles : 3;
            for (int st = 0; st < pre; st++) {
                int rows = min(TR, nrows - st * TR);
                tile_issue(bufu + st * TILE_BYTES, Wout + (long)(r0 + st * TR) * H,
                           rows * H * 4, mb2 + 8 * st);
            }
        }
        for (int i = 0; i < ntiles; i++) {
            int slot = i % 3;
            mbar_wait(mb2 + 8 * slot, (i / 3) & 1);
            int trows = min(TR, nrows - i * TR);
            if (warp < trows) {
                int r = r0 + i * TR + warp;
                float acc = smem_row_dot(dynbuf + slot * TILE_FLOATS + warp * H, sx4, lane);
                acc = warp_sum(acc);
                if (lane == 0) {
                    float v = acc + bout[r];
                    out[r] = v;
                    merge_pair(m, s, v, 1.0f);
                }
            }
            __syncthreads();
            if (t == 0 && i + 3 < ntiles) {
                fence_async();
                int rows = min(TR, nrows - (i + 3) * TR);
                tile_issue(bufu + slot * TILE_BYTES, Wout + (long)(r0 + (i + 3) * TR) * H,
                           rows * H * 4, mb2 + 8 * slot);
            }
        }
    }
    if (lane == 0) spair[warp] = make_float2(m, s);
    __syncthreads();
    if (t == 0) {
        float mm = spair[0].x, ss = spair[0].y;
#pragma unroll
        for (int wq = 1; wq < 16; wq++) merge_pair(mm, ss, spair[wq].x, spair[wq].y);
        g_pairs[b] = make_float2(mm, ss);
    }
    gsync(2);

    // P6: every block redundantly reduces g_pairs (identical order/bits),
    // then subtracts lse from its slice.
    {
        float mm = -INFINITY, ss = 0.f;
        if (t < NB) { float2 p = g_pairs[t]; mm = p.x; ss = p.y; }
#pragma unroll
        for (int o = 16; o > 0; o >>= 1) {
            float m2 = __shfl_down_sync(0xffffffffu, mm, o);
            float s2 = __shfl_down_sync(0xffffffffu, ss, o);
            merge_pair(mm, ss, m2, s2);
        }
        if (lane == 0 && warp < 5) spair[warp] = make_float2(mm, ss);
        __syncthreads();
        if (t == 0) {
            mm = spair[0].x; ss = spair[0].y;
#pragma unroll
            for (int wq = 1; wq < 5; wq++) merge_pair(mm, ss, spair[wq].x, spair[wq].y);
            s_lse = mm + logf(ss);
        }
        __syncthreads();
    }
    int i = b * LOG_CHUNK + t;
    if (t < LOG_CHUNK && i < VOCAB) out[i] -= s_lse;
}

// ---------------------------------------------------------------------------
extern "C" void kernel_launch(void* const* d_in, const int* in_sizes, int n_in,
                              void* d_out, int out_size) {
    const int*   id   = (const int*)d_in[0];
    const float* h0   = (const float*)d_in[1];
    const float* c0   = (const float*)d_in[2];
    const float* emb  = (const float*)d_in[3];
    const float* Wih  = (const float*)d_in[4];
    const float* Whh  = (const float*)d_in[5];
    const float* bih  = (const float*)d_in[6];
    const float* bhh  = (const float*)d_in[7];
    const float* Wout = (const float*)d_in[8];
    const float* bout = (const float*)d_in[9];
    float* out = (float*)d_out;

    int write_tail = (out_size >= VOCAB + 2 * H) ? 1 : 0;

    cudaFuncSetAttribute(decoder_kernel,
                         cudaFuncAttributeMaxDynamicSharedMemorySize, DYN_SMEM);
    decoder_kernel<<<NB, NT, DYN_SMEM>>>(id, h0, c0, emb, Wih, Whh, bih, bhh,
                                         Wout, bout, out, write_tail);
}

// round 12
// speedup vs baseline: 1.0852x; 1.0852x over previous
#include <cuda_runtime.h>
#include <math.h>

#define H 1024
#define VOCAB 50257
#define NB 148                  // persistent: one block per SM
#define NT 1024
#define NW (NB * 32)            // 4736 warps
#define FIN_CHUNK 340           // ceil(VOCAB / NB)

// Scratch (__device__ globals — allocation-free rule)
__device__ float g_partA[8192];     // layer1 partials: [0,4096)=Wih, [4096,8192)=Whh
__device__ float g_partB[8192];     // layer2 partials
__device__ float2 g_pairs[NB];
__device__ unsigned g_cnt[4];
__device__ volatile unsigned g_gen[4];

// ---------------------------------------------------------------------------
__device__ __forceinline__ float sigmoidf_fast(float x) {
    return 1.f / (1.f + __expf(-x));
}

__device__ __forceinline__ void merge_pair(float& m, float& s, float m2, float s2) {
    if (m2 > m) { float t = s; s = s2 + t * __expf(m - m2); m = m2; }
    else if (m2 != -INFINITY) { s += s2 * __expf(m2 - m); }
}

// Grid-wide spin barrier. Safe because all NB blocks are co-resident.
__device__ __forceinline__ void gsync(int b) {
    __syncthreads();
    if (threadIdx.x == 0) {
        __threadfence();
        unsigned cur = g_gen[b];
        unsigned pos = atomicAdd(&g_cnt[b], 1u);
        if (pos == NB - 1) {
            g_cnt[b] = 0;
            __threadfence();
            g_gen[b] = cur + 1;
        } else {
            while (g_gen[b] == cur) __nanosleep(64);
        }
        __threadfence();
    }
    __syncthreads();
}

// Fire-and-forget L2 fill: touch one 128B line per call, result discarded.
// No consumer => warp never stalls on it; fills idle DRAM slots.
__device__ __forceinline__ void l2_touch(const float* p) {
    float d;
    asm volatile("ld.global.nc.b32 %0, [%1];" : "=f"(d) : "l"(p));
}

// 256-bit loads (sm_103a)
struct f8 { float4 a, b; };

__device__ __forceinline__ f8 ld8(const float* p) {
    f8 v;
    asm volatile(
        "{\n\t.reg .b64 q0,q1,q2,q3;\n\t"
        "ld.global.nc.v4.b64 {q0,q1,q2,q3}, [%8];\n\t"
        "mov.b64 {%0,%1}, q0;\n\tmov.b64 {%2,%3}, q1;\n\t"
        "mov.b64 {%4,%5}, q2;\n\tmov.b64 {%6,%7}, q3;\n\t}"
        : "=f"(v.a.x), "=f"(v.a.y), "=f"(v.a.z), "=f"(v.a.w),
          "=f"(v.b.x), "=f"(v.b.y), "=f"(v.b.z), "=f"(v.b.w)
        : "l"(p));
    return v;
}

__device__ __forceinline__ void row_load(const float* W, int lane, f8 w[4]) {
#pragma unroll
    for (int k = 0; k < 4; k++) w[k] = ld8(W + (k * 32 + lane) * 8);
}

__device__ __forceinline__ float dot8(const f8& w, const float4& x0, const float4& x1) {
    return w.a.x * x0.x + w.a.y * x0.y + w.a.z * x0.z + w.a.w * x0.w
         + w.b.x * x1.x + w.b.y * x1.y + w.b.z * x1.z + w.b.w * x1.w;
}

__device__ __forceinline__ float row_dot(const f8 w[4], const float4* v4, int lane) {
    float acc = 0.f;
#pragma unroll
    for (int k = 0; k < 4; k++) {
        int c = (k * 32 + lane) * 2;
        acc += dot8(w[k], v4[c], v4[c + 1]);
    }
    return acc;
}

__device__ __forceinline__ float warp_sum(float acc) {
#pragma unroll
    for (int o = 16; o > 0; o >>= 1) acc += __shfl_down_sync(0xffffffffu, acc, o);
    return acc;
}

// LSTM elementwise for element j (torch gate order i, f, g, o)
__device__ __forceinline__ void act_phase(
        const float* __restrict__ part,
        const float* __restrict__ bih, const float* __restrict__ bhh,
        float cin, float& hout, float& cout, int j) {
    float gi = part[j]         + part[4096 + j]         + bih[j]         + bhh[j];
    float gf = part[j + H]     + part[4096 + j + H]     + bih[j + H]     + bhh[j + H];
    float gg = part[j + 2 * H] + part[4096 + j + 2 * H] + bih[j + 2 * H] + bhh[j + 2 * H];
    float go = part[j + 3 * H] + part[4096 + j + 3 * H] + bih[j + 3 * H] + bhh[j + 3 * H];
    cout = sigmoidf_fast(gf) * cin + sigmoidf_fast(gi) * tanhf(gg);
    hout = sigmoidf_fast(go) * tanhf(cout);
}

// ---------------------------------------------------------------------------
// Gates GEMV phase: 8192 virtual rows over NW warps, 1 row per step.
// vr < 4096: Wih vs sx (relu'd x).  vr >= 4096: Whh vs sh (h).
// Zero-source rows: no loads, partial = 0.
// ---------------------------------------------------------------------------
__device__ __forceinline__ void gates_phase(
        const float* __restrict__ Wih, const float* __restrict__ Whh,
        const float4* sx4, const float4* sh4, float* __restrict__ part,
        int gw, int lane, bool xz, bool hz) {
    for (int vr = gw; vr < 8192; vr += NW) {
        bool isA = vr < 4096;
        bool active = isA ? !xz : !hz;
        float acc = 0.f;
        if (active) {
            const float* W = (isA ? Wih : Whh) + (long)(vr & 4095) * H;
            f8 w[4];
            row_load(W, lane, w);
            acc = row_dot(w, isA ? sx4 : sh4, lane);
        }
        acc = warp_sum(acc);
        if (lane == 0) part[vr] = acc;
    }
}

// ---------------------------------------------------------------------------
// ONE persistent kernel: embed -> gates1 -> act1 -> gates2 -> act2 ->
// logits (+online softmax pairs) -> lse -> subtract. 3 grid barriers.
// ---------------------------------------------------------------------------
__global__ void __launch_bounds__(NT, 1) decoder_kernel(
        const int* __restrict__ id, const float* __restrict__ h0,
        const float* __restrict__ c0, const float* __restrict__ emb,
        const float* __restrict__ Wih, const float* __restrict__ Whh,
        const float* __restrict__ bih, const float* __restrict__ bhh,
        const float* __restrict__ Wout, const float* __restrict__ bout,
        float* __restrict__ out, int write_tail) {
    __shared__ float sx[H];
    __shared__ float sh[H];
    __shared__ float2 spair[32];
    __shared__ float s_lse;
    __shared__ int s_nzx, s_nzh;

    int t = threadIdx.x, lane = t & 31, warp = t >> 5, b = blockIdx.x;
    int gw = b * 32 + warp;
    long gtid = (long)b * NT + t;           // [0, 151552)
    const float4* sx4 = (const float4*)sx;
    const float4* sh4 = (const float4*)sh;

    // P0: stage relu(emb[id]) and h0; detect all-zero source vectors
    if (t == 0) { s_nzx = 0; s_nzh = 0; }
    __syncthreads();
    {
        float xv = fmaxf(emb[(long)id[0] * H + t], 0.f);
        float hv = h0[t];
        sx[t] = xv; sh[t] = hv;
        if (xv != 0.f) s_nzx = 1;
        if (hv != 0.f) s_nzh = 1;
    }
    __syncthreads();

    // P1: layer-1 gates GEMV (Whh half skipped when h0 == 0)
    gates_phase(Wih, Whh, sx4, sh4, g_partA, gw, lane, !s_nzx, !s_nzh);
    // window A: pre-stage W_out rows [0, 4736) into L2 (1 line per thread);
    // these are exactly the rows logits iteration 0 reads.
    l2_touch(Wout + gtid * 32);
    gsync(0);

    // P2: act1 — redundant per block; c1 stays in a register
    float h1, c1;
    act_phase(g_partA, bih, bhh, c0[t], h1, c1, t);
    __syncthreads();
    if (t == 0) { s_nzx = 0; s_nzh = 0; }
    __syncthreads();
    {
        float xv = fmaxf(h1, 0.f);
        sx[t] = xv; sh[t] = h1;
        if (xv != 0.f) s_nzx = 1;
        if (h1 != 0.f) s_nzh = 1;
    }
    __syncthreads();

    // P3: layer-2 gates GEMV — reads are L2 hits (layer-1 pulled Wih/Whh),
    // so DRAM is idle here: pre-stage W_out rows [4736, 14208) (2 lines/thread).
    gates_phase(Wih, Whh, sx4, sh4, g_partB, gw, lane, !s_nzx, !s_nzh);
    l2_touch(Wout + (long)4736 * H + gtid * 32);
    l2_touch(Wout + (long)9472 * H + gtid * 32);
    gsync(1);

    // P4: act2 — redundant per block; block 0 writes the (h, c) tail
    float h2, c2;
    act_phase(g_partB, bih, bhh, c1, h2, c2, t);
    __syncthreads();
    sx[t] = h2;
    if (write_tail && b == 0) {
        out[VOCAB + t]     = h2;
        out[VOCAB + H + t] = c2;
    }
    __syncthreads();

    // P5: logits GEMV + per-warp online (max, sumexp)
    float m = -INFINITY, s = 0.f;
    for (int row = gw; row < VOCAB; row += NW) {
        const float* p = Wout + (long)row * H;
        f8 w[4];
        row_load(p, lane, w);
        float acc = row_dot(w, sx4, lane);
        acc = warp_sum(acc);
        if (lane == 0) {
            float v = acc + bout[row];
            out[row] = v;
            merge_pair(m, s, v, 1.0f);
        }
    }
    if (lane == 0) spair[warp] = make_float2(m, s);
    __syncthreads();
    if (t == 0) {
        float mm = spair[0].x, ss = spair[0].y;
#pragma unroll
        for (int wq = 1; wq < 32; wq++) merge_pair(mm, ss, spair[wq].x, spair[wq].y);
        g_pairs[b] = make_float2(mm, ss);
    }
    gsync(2);

    // P6: every block redundantly reduces g_pairs (identical order => identical
    // bits), then subtracts lse from its slice of out.
    {
        float mm = -INFINITY, ss = 0.f;
        if (t < NB) { float2 p = g_pairs[t]; mm = p.x; ss = p.y; }
#pragma unroll
        for (int o = 16; o > 0; o >>= 1) {
            float m2 = __shfl_down_sync(0xffffffffu, mm, o);
            float s2 = __shfl_down_sync(0xffffffffu, ss, o);
            merge_pair(mm, ss, m2, s2);
        }
        if (lane == 0 && warp < 5) spair[warp] = make_float2(mm, ss);
        __syncthreads();
        if (t == 0) {
            mm = spair[0].x; ss = spair[0].y;
#pragma unroll
            for (int wq = 1; wq < 5; wq++) merge_pair(mm, ss, spair[wq].x, spair[wq].y);
            s_lse = mm + logf(ss);
        }
        __syncthreads();
    }
    int i = b * FIN_CHUNK + t;
    if (t < FIN_CHUNK && i < VOCAB) out[i] -= s_lse;
}

// ---------------------------------------------------------------------------
extern "C" void kernel_launch(void* const* d_in, const int* in_sizes, int n_in,
                              void* d_out, int out_size) {
    const int*   id   = (const int*)d_in[0];
    const float* h0   = (const float*)d_in[1];
    const float* c0   = (const float*)d_in[2];
    const float* emb  = (const float*)d_in[3];
    const float* Wih  = (const float*)d_in[4];
    const float* Whh  = (const float*)d_in[5];
    const float* bih  = (const float*)d_in[6];
    const float* bhh  = (const float*)d_in[7];
    const float* Wout = (const float*)d_in[8];
    const float* bout = (const float*)d_in[9];
    float* out = (float*)d_out;

    int write_tail = (out_size >= VOCAB + 2 * H) ? 1 : 0;

    decoder_kernel<<<NB, NT>>>(id, h0, c0, emb, Wih, Whh, bih, bhh,
                               Wout, bout, out, write_tail);
}